// round 9
// baseline (speedup 1.0000x reference)
#include <cuda_runtime.h>

#define EPS 0.1f
#define BB 64
#define II 1024
#define HH 4096
#define OO 256

__device__ float        g_w1norm[HH];
__device__ float        g_nnpart[OO * 4];
__device__ unsigned int g_ctr;          // zero-init, monotonic across replays

// ---------------------------------------------------------------------------
// Single fused kernel. Grid = EXACTLY 1024 blocks x 256 threads.
//   __launch_bounds__(256,7): regs<=36 -> 7 blocks/SM -> 1036 slots >= 1024,
//   so all blocks are resident in wave 1 and the spin barrier cannot deadlock.
//
//   phase 1 (all blocks, uniform):
//     - w1norm for rows [4*bid, 4*bid+4)  (half-row per warp)
//     - load own pert W2 float4 (kept in regs, reused in phase 2)
//     - nn partial for (i,c) from those same W2 values
//     - stage yf
//   barrier: threadfence + monotonic ticket (epoch = ticket/1024, no reset)
//   phase 2:
//     - c==0 blocks: fixed-order sum of 4 partials -> nn_output fanout
//     - all blocks: pert store stream (exact R2 path)
// ---------------------------------------------------------------------------
__global__ void __launch_bounds__(256, 7)
k_fused(const int*   __restrict__ y,
        const float* __restrict__ W1,
        const float* __restrict__ W2,
        const float* __restrict__ bias2,
        float* __restrict__ out_nn,
        float* __restrict__ pert)
{
    const int bid = blockIdx.x;          // 0..1023
    const int i   = bid >> 2;            // W2 row / output column
    const int c   = bid & 3;             // j-chunk
    const int tid = threadIdx.x;
    const int lid = tid & 31;
    const int wid = tid >> 5;
    const int j4  = c * 256 + tid;       // float4 index within row i

    __shared__ float yf[BB];
    __shared__ float smW1[8];
    __shared__ float smW2[8];
    __shared__ float s_tot;
    __shared__ unsigned int s_target;

    // ---------------- phase 1: issue all independent loads ----------------
    // pert's own W2 float4 (kept for phase 2 — no reread)
    float4 w = reinterpret_cast<const float4*>(W2 + (size_t)i * HH)[j4];

    // W1 rows [4*bid, 4*bid+4): warp (wid) takes half-row (wid&1) of row 4*bid+(wid>>1)
    const int row  = 4 * bid + (wid >> 1);
    const int half = wid & 1;
    const float4* r = reinterpret_cast<const float4*>(W1 + (size_t)row * II) + half * 128;
    float4 v0 = r[lid], v1 = r[lid + 32], v2 = r[lid + 64], v3 = r[lid + 96];

    if (tid < BB) yf[tid] = (float)y[(size_t)tid * OO + i];

    // reduce |W1| half-row
    float a = fabsf(v0.x) + fabsf(v0.y) + fabsf(v0.z) + fabsf(v0.w)
            + fabsf(v1.x) + fabsf(v1.y) + fabsf(v1.z) + fabsf(v1.w)
            + fabsf(v2.x) + fabsf(v2.y) + fabsf(v2.z) + fabsf(v2.w)
            + fabsf(v3.x) + fabsf(v3.y) + fabsf(v3.z) + fabsf(v3.w);
    // reduce W2 partial (nn)
    float ps = w.x + w.y + w.z + w.w;
    #pragma unroll
    for (int o = 16; o; o >>= 1) {
        a  += __shfl_down_sync(0xffffffffu, a,  o);
        ps += __shfl_down_sync(0xffffffffu, ps, o);
    }
    if (lid == 0) { smW1[wid] = a; smW2[wid] = ps; }
    __syncthreads();
    if (tid < 4)   // combine halves in fixed order: deterministic
        g_w1norm[4 * bid + tid] = smW1[2 * tid] + smW1[2 * tid + 1];
    if (tid == 4) {
        float t = ((smW2[0] + smW2[1]) + (smW2[2] + smW2[3]))
                + ((smW2[4] + smW2[5]) + (smW2[6] + smW2[7]));
        g_nnpart[bid] = t;
    }

    // ---------------- barrier (release / monotonic ticket / acquire) -------
    __threadfence();
    if (tid == 0) {
        unsigned int t = atomicAdd(&g_ctr, 1u);
        s_target = ((t >> 10) + 1u) << 10;          // (epoch+1)*1024
        while (*(volatile unsigned int*)&g_ctr < s_target)
            __nanosleep(64);
    }
    __syncthreads();

    // ---------------- phase 2a: nn fanout (c==0 blocks only) ---------------
    if (c == 0) {
        if (tid == 0) {
            const float* p4 = g_nnpart + i * 4;     // fixed order -> deterministic
            float tot = (__ldcg(p4 + 0) + __ldcg(p4 + 1))
                      + (__ldcg(p4 + 2) + __ldcg(p4 + 3));
            s_tot = tot * (float)HH + bias2[i];
        }
        __syncthreads();
        if (tid < BB)
            out_nn[(size_t)tid * OO + i] = s_tot;
    }

    // ---------------- phase 2b: pert store stream (exact R2 path) ----------
    float4 n = __ldcg(reinterpret_cast<const float4*>(g_w1norm) + j4);
    float4 s;
    s.x = -EPS * ((w.x > 0.f) ? 1.f : (w.x < 0.f) ? -1.f : 0.f) * n.x;
    s.y = -EPS * ((w.y > 0.f) ? 1.f : (w.y < 0.f) ? -1.f : 0.f) * n.y;
    s.z = -EPS * ((w.z > 0.f) ? 1.f : (w.z < 0.f) ? -1.f : 0.f) * n.z;
    s.w = -EPS * ((w.w > 0.f) ? 1.f : (w.w < 0.f) ? -1.f : 0.f) * n.w;

    float* base = pert + (size_t)i * HH + (size_t)j4 * 4;
    #pragma unroll 8
    for (int b = 0; b < BB; b++) {
        float yb = yf[b];
        float4 o;
        o.x = yb * s.x; o.y = yb * s.y; o.z = yb * s.z; o.w = yb * s.w;
        __stcs(reinterpret_cast<float4*>(base + (size_t)b * OO * HH), o);
    }
}

// ---------------------------------------------------------------------------
// launch — single kernel
// inputs: x[0] (unused), y[1], W1[2], W2[3], bias1[4] (unused), bias2[5]
// out layout: nn_output [B*O] then pert [B*O*H]
// ---------------------------------------------------------------------------
extern "C" void kernel_launch(void* const* d_in, const int* in_sizes, int n_in,
                              void* d_out, int out_size) {
    const int*   y     = (const int*)d_in[1];
    const float* W1    = (const float*)d_in[2];
    const float* W2    = (const float*)d_in[3];
    const float* bias2 = (const float*)d_in[5];

    float* out_nn = (float*)d_out;
    float* pert   = out_nn + (size_t)BB * OO;

    k_fused<<<1024, 256>>>(y, W1, W2, bias2, out_nn, pert);
}

// round 10
// speedup vs baseline: 1.1327x; 1.1327x over previous
#include <cuda_runtime.h>

#define EPS 0.1f
#define BB 64
#define II 1024
#define HH 4096
#define OO 256

__device__ float g_w1norm[HH];

// ---------------------------------------------------------------------------
// K1: W1_norm[j] = sum_i |W1[j,i]|
//   2048 blocks x 64 threads (2 warps); one warp per row; 8 LDG.128/thread
//   in flight. Fine-grained blocks -> ~7% wave imbalance (vs 33% at 512x256).
//   Triggers programmatic launch completion immediately so k_main's blocks
//   can start their independent loads while this kernel streams W1.
// ---------------------------------------------------------------------------
__global__ void k_w1norm(const float* __restrict__ W1) {
#if __CUDA_ARCH__ >= 900
    cudaTriggerProgrammaticLaunchCompletion();
#endif
    const int lid = threadIdx.x & 31;
    const int row = blockIdx.x * 2 + (threadIdx.x >> 5);
    const float4* r = reinterpret_cast<const float4*>(W1 + (size_t)row * II);
    float4 v[8];
    #pragma unroll
    for (int k = 0; k < 8; k++) v[k] = r[lid + k * 32];
    float s = 0.f;
    #pragma unroll
    for (int k = 0; k < 8; k++)
        s += fabsf(v[k].x) + fabsf(v[k].y) + fabsf(v[k].z) + fabsf(v[k].w);
    #pragma unroll
    for (int o = 16; o; o >>= 1) s += __shfl_down_sync(0xffffffffu, s, o);
    if (lid == 0) g_w1norm[row] = s;
}

// ---------------------------------------------------------------------------
// K2: fused nn_output + pert — R3 structure (best measured), PDL-overlapped.
//   grid = 256 + 1024 blocks, 256 threads.
//   bid <  256 : nn_output row i = bid (independent of w1norm -> no grid sync)
//   bid >= 256 : pert unit p = bid-256 (i = p>>2, chunk = p&3):
//                load W2/y first (independent), THEN gridDependencySync,
//                THEN read g_w1norm.
// ---------------------------------------------------------------------------
__global__ void k_main(const int* __restrict__ y,
                       const float* __restrict__ W2,
                       const float* __restrict__ bias2,
                       float* __restrict__ out_nn,
                       float* __restrict__ pert) {
    const int bid = blockIdx.x;
    const int lid = threadIdx.x & 31;
    const int wid = threadIdx.x >> 5;

    if (bid < 256) {
        // ---- nn_output row i (no w1norm dependency, runs fully overlapped) ----
        const int i = bid;
        const float4* r = reinterpret_cast<const float4*>(W2 + (size_t)i * HH);
        float4 v[4];
        #pragma unroll
        for (int k = 0; k < 4; k++) v[k] = r[threadIdx.x + k * 256];
        float s = 0.f;
        #pragma unroll
        for (int k = 0; k < 4; k++) s += v[k].x + v[k].y + v[k].z + v[k].w;

        __shared__ float sm[8];
        #pragma unroll
        for (int o = 16; o; o >>= 1) s += __shfl_down_sync(0xffffffffu, s, o);
        if (lid == 0) sm[wid] = s;
        __syncthreads();
        __shared__ float total;
        if (threadIdx.x < 8) {
            float t = sm[threadIdx.x];
            #pragma unroll
            for (int o = 4; o; o >>= 1) t += __shfl_down_sync(0xffu, t, o);
            if (threadIdx.x == 0) total = t * (float)HH + bias2[i];
        }
        __syncthreads();
        if (threadIdx.x < BB)
            out_nn[(size_t)threadIdx.x * OO + i] = total;
        return;
    }

    // ---- pert ----
    const int p  = bid - 256;
    const int i  = p >> 2;
    const int j4 = (p & 3) * 256 + threadIdx.x;

    __shared__ float yf[BB];
    if (threadIdx.x < BB) yf[threadIdx.x] = (float)y[(size_t)threadIdx.x * OO + i];

    // independent load first (overlaps with w1norm's tail under PDL)
    float4 w = reinterpret_cast<const float4*>(W2 + (size_t)i * HH)[j4];

#if __CUDA_ARCH__ >= 900
    cudaGridDependencySynchronize();   // wait for k_w1norm completion+visibility
#endif
    __syncthreads();                    // covers yf

    float4 n = reinterpret_cast<const float4*>(g_w1norm)[j4];
    float4 s;
    s.x = -EPS * ((w.x > 0.f) ? 1.f : (w.x < 0.f) ? -1.f : 0.f) * n.x;
    s.y = -EPS * ((w.y > 0.f) ? 1.f : (w.y < 0.f) ? -1.f : 0.f) * n.y;
    s.z = -EPS * ((w.z > 0.f) ? 1.f : (w.z < 0.f) ? -1.f : 0.f) * n.z;
    s.w = -EPS * ((w.w > 0.f) ? 1.f : (w.w < 0.f) ? -1.f : 0.f) * n.w;

    float* base = pert + (size_t)i * HH + (size_t)j4 * 4;
    #pragma unroll 8
    for (int b = 0; b < BB; b++) {
        float yb = yf[b];
        float4 o;
        o.x = yb * s.x; o.y = yb * s.y; o.z = yb * s.z; o.w = yb * s.w;
        __stcs(reinterpret_cast<float4*>(base + (size_t)b * OO * HH), o);
    }
}

// ---------------------------------------------------------------------------
// launch — w1norm, then k_main as a programmatic dependent launch
// inputs: x[0] (unused), y[1], W1[2], W2[3], bias1[4] (unused), bias2[5]
// out layout: nn_output [B*O] then pert [B*O*H]
// ---------------------------------------------------------------------------
extern "C" void kernel_launch(void* const* d_in, const int* in_sizes, int n_in,
                              void* d_out, int out_size) {
    const int*   y     = (const int*)d_in[1];
    const float* W1    = (const float*)d_in[2];
    const float* W2    = (const float*)d_in[3];
    const float* bias2 = (const float*)d_in[5];

    float* out_nn = (float*)d_out;
    float* pert   = out_nn + (size_t)BB * OO;

    k_w1norm<<<2048, 64>>>(W1);

    cudaLaunchAttribute attrs[1];
    attrs[0].id = cudaLaunchAttributeProgrammaticStreamSerialization;
    attrs[0].val.programmaticStreamSerializationAllowed = 1;

    cudaLaunchConfig_t cfg = {};
    cfg.gridDim  = dim3(256 + 1024);
    cfg.blockDim = dim3(256);
    cfg.dynamicSmemBytes = 0;
    cfg.stream   = 0;
    cfg.attrs    = attrs;
    cfg.numAttrs = 1;
    cudaLaunchKernelEx(&cfg, k_main, y, W2, bias2, out_nn, pert);
}